// round 6
// baseline (speedup 1.0000x reference)
#include <cuda_runtime.h>
#include <cstdint>

// Problem constants (fixed: B=4, T=2048, C=1024, H=16)
#define B_  4
#define T_  2048
#define C_  1024
#define H_  16
#define HS_ 64
#define M_  (B_ * T_)     // 8192
#define N3_ (3 * C_)      // 3072
#define K_  C_            // 1024

// Scratch (__device__ globals).
__device__ float g_q [(size_t)B_ * H_ * T_ * HS_];   // tf32, pre-scaled 0.125
__device__ float g_k [(size_t)B_ * H_ * T_ * HS_];   // tf32
__device__ float g_vt[(size_t)B_ * H_ * HS_ * T_];   // tf32, transposed [d][t]
__device__ float g_xr[(size_t)M_ * K_];              // tf32-rounded x
__device__ float g_wr[(size_t)N3_ * K_];             // tf32-rounded W

// ---------------------------------------------------------------------------
__device__ __forceinline__ uint32_t smem_u32(const void* p) {
    uint32_t a;
    asm("{ .reg .u64 t; cvta.to.shared.u64 t, %1; cvt.u32.u64 %0, t; }"
        : "=r"(a) : "l"(p));
    return a;
}
__device__ __forceinline__ float to_tf32(float x) {
    uint32_t u;
    asm("cvt.rna.tf32.f32 %0, %1;" : "=r"(u) : "f"(x));
    return __uint_as_float(u);
}
__device__ __forceinline__ void ldsm4(uint32_t& r0, uint32_t& r1,
                                      uint32_t& r2, uint32_t& r3, uint32_t addr) {
    asm volatile("ldmatrix.sync.aligned.m8n8.x4.shared.b16 {%0,%1,%2,%3}, [%4];"
                 : "=r"(r0), "=r"(r1), "=r"(r2), "=r"(r3) : "r"(addr));
}
__device__ __forceinline__ void mma_tf32(float* c, const uint32_t* a,
                                         uint32_t b0, uint32_t b1) {
    asm volatile(
        "mma.sync.aligned.m16n8k8.row.col.f32.tf32.tf32.f32 "
        "{%0,%1,%2,%3}, {%4,%5,%6,%7}, {%8,%9}, {%0,%1,%2,%3};"
        : "+f"(c[0]), "+f"(c[1]), "+f"(c[2]), "+f"(c[3])
        : "r"(a[0]), "r"(a[1]), "r"(a[2]), "r"(a[3]), "r"(b0), "r"(b1));
}
__device__ __forceinline__ void cp16(uint32_t dst_smem, const void* src) {
    asm volatile("cp.async.cg.shared.global [%0], [%1], 16;"
                 :: "r"(dst_smem), "l"(src));
}
// Swizzled byte offsets (XOR bank-quad with row%8). Rows 128B / 256B.
__device__ __forceinline__ uint32_t sw128(int row, int colf) {
    return (uint32_t)(row * 128 + colf * 4) ^ (uint32_t)((row & 7) << 4);
}
__device__ __forceinline__ uint32_t sw256(int row, int colf) {
    return (uint32_t)(row * 256 + colf * 4) ^ (uint32_t)((row & 7) << 4);
}

// ---------------------------------------------------------------------------
// Kernel 0: round x and W to tf32 scratch.
// ---------------------------------------------------------------------------
#define NX4 (M_ * K_ / 4)
#define NW4 (N3_ * K_ / 4)

__global__ __launch_bounds__(256)
void round_inputs(const float* __restrict__ x, const float* __restrict__ W) {
    int i = blockIdx.x * 256 + threadIdx.x;
    if (i < NX4) {
        float4 v = ((const float4*)x)[i];
        v.x = to_tf32(v.x); v.y = to_tf32(v.y);
        v.z = to_tf32(v.z); v.w = to_tf32(v.w);
        ((float4*)g_xr)[i] = v;
    } else {
        int j = i - NX4;
        float4 v = ((const float4*)W)[j];
        v.x = to_tf32(v.x); v.y = to_tf32(v.y);
        v.z = to_tf32(v.z); v.w = to_tf32(v.w);
        ((float4*)g_wr)[j] = v;
    }
}

// ---------------------------------------------------------------------------
// Kernel 1: QKV GEMM, tf32 mma.sync.  CTA 128x256, BK=32, 8 warps (2x4),
// warp tile 64x64 (32 FLOP/LDS-byte), 4-stage cp.async, swizzled smem.
// ---------------------------------------------------------------------------
#define GM_STAGE_B 49152                     // (128+256)*32*4
#define GM_STAGES  4
#define GM_SMEM_BYTES (GM_STAGES * GM_STAGE_B)   // 196608
#define GM_KT (K_ / 32)                      // 32

__global__ __launch_bounds__(256, 1)
void qkv_gemm_tc(const float* __restrict__ bias) {
    extern __shared__ float sm[];
    const uint32_t sb = smem_u32(sm);
    const int tid  = threadIdx.x;
    const int lane = tid & 31;
    const int w    = tid >> 5;
    const int wm   = w >> 2;                 // 0..1 (64-row block)
    const int wn   = w & 3;                  // 0..3 (64-col block)
    const int row0 = blockIdx.y * 128;
    const int col0 = blockIdx.x * 256;

    float acc[4][8][4];
#pragma unroll
    for (int i = 0; i < 4; i++)
#pragma unroll
        for (int j = 0; j < 8; j++)
#pragma unroll
            for (int e = 0; e < 4; e++) acc[i][j][e] = 0.0f;

    const int lr = tid >> 3;                 // 0..31
    const int lc = (tid & 7) * 4;            // 0..28
#define GM_LOAD(kt) do {                                                       \
    uint32_t aOff_ = sb + ((kt) & (GM_STAGES - 1)) * GM_STAGE_B;               \
    uint32_t bOff_ = aOff_ + 16384;                                            \
    const float* Ab_ = g_xr + (size_t)row0 * K_ + (kt) * 32;                   \
    const float* Bb_ = g_wr + (size_t)col0 * K_ + (kt) * 32;                   \
    _Pragma("unroll")                                                          \
    for (int q_ = 0; q_ < 4; q_++) {                                           \
        int r_ = lr + q_ * 32;                                                 \
        cp16(aOff_ + sw128(r_, lc), Ab_ + (size_t)r_ * K_ + lc);               \
    }                                                                          \
    _Pragma("unroll")                                                          \
    for (int q_ = 0; q_ < 8; q_++) {                                           \
        int r_ = lr + q_ * 32;                                                 \
        cp16(bOff_ + sw128(r_, lc), Bb_ + (size_t)r_ * K_ + lc);               \
    }                                                                          \
    asm volatile("cp.async.commit_group;" ::: "memory");                       \
} while (0)

    GM_LOAD(0);
    GM_LOAD(1);
    GM_LOAD(2);

    const int aRow  = lane & 15;
    const int aCol  = (lane >> 4) * 4;
    const int bRowO = ((lane & 16) ? 8 : 0) + (lane & 7);
    const int bColO = (lane & 8) ? 4 : 0;

    for (int kt = 0; kt < GM_KT; kt++) {
        if (kt + 1 < GM_KT) asm volatile("cp.async.wait_group 2;" ::: "memory");
        else                asm volatile("cp.async.wait_group 0;" ::: "memory");
        __syncthreads();

        const uint32_t aBase = sb + (kt & (GM_STAGES - 1)) * GM_STAGE_B;
        const uint32_t bBase = aBase + 16384;

#pragma unroll
        for (int ks = 0; ks < 4; ks++) {
            const int kc = ks * 8;
            uint32_t a[4][4];
#pragma unroll
            for (int i = 0; i < 4; i++) {
                int row = wm * 64 + i * 16 + aRow;
                ldsm4(a[i][0], a[i][1], a[i][2], a[i][3],
                      aBase + sw128(row, kc + aCol));
            }
            uint32_t bf[4][4];
#pragma unroll
            for (int p = 0; p < 4; p++) {
                int n = wn * 64 + p * 16 + bRowO;
                ldsm4(bf[p][0], bf[p][1], bf[p][2], bf[p][3],
                      bBase + sw128(n, kc + bColO));
            }
#pragma unroll
            for (int i = 0; i < 4; i++)
#pragma unroll
                for (int j = 0; j < 8; j++)
                    mma_tf32(acc[i][j], a[i],
                             bf[j >> 1][(j & 1) * 2], bf[j >> 1][(j & 1) * 2 + 1]);
        }
        if (kt + 3 < GM_KT) GM_LOAD(kt + 3);
    }

    // ---- epilogue: bias, tf32 round, scatter ----
    const int g  = lane >> 2;
    const int t2 = (lane & 3) * 2;
    const int sQ = col0 >> 10;                        // 0:q 1:k 2:v (256|1024)
    const int h  = ((col0 + wn * 64) >> 6) & (H_ - 1);

    float rb[8][2];
#pragma unroll
    for (int j = 0; j < 8; j++) {
        rb[j][0] = __ldg(bias + col0 + wn * 64 + j * 8 + t2);
        rb[j][1] = __ldg(bias + col0 + wn * 64 + j * 8 + t2 + 1);
    }

#pragma unroll
    for (int i = 0; i < 4; i++) {
        int m    = row0 + wm * 64 + i * 16 + g;
        int bidx = m >> 11;
        int ti   = m & (T_ - 1);
#pragma unroll
        for (int j = 0; j < 8; j++) {
            int d = j * 8 + t2;
            float c0 = acc[i][j][0] + rb[j][0];
            float c1 = acc[i][j][1] + rb[j][1];
            float c2 = acc[i][j][2] + rb[j][0];
            float c3 = acc[i][j][3] + rb[j][1];
            if (sQ == 0) {
                c0 *= 0.125f; c1 *= 0.125f; c2 *= 0.125f; c3 *= 0.125f;
            }
            c0 = to_tf32(c0); c1 = to_tf32(c1);
            c2 = to_tf32(c2); c3 = to_tf32(c3);
            if (sQ == 2) {
                float* p = g_vt + (((size_t)bidx * H_ + h) * HS_ + d) * T_ + ti;
                p[0]      = c0;  p[T_]     = c1;
                p[8]      = c2;  p[T_ + 8] = c3;
            } else {
                float* dst = (sQ == 0) ? g_q : g_k;
                float* p = dst + (((size_t)bidx * H_ + h) * T_ + ti) * HS_ + d;
                *(float2*)p             = make_float2(c0, c1);
                *(float2*)(p + 8 * HS_) = make_float2(c2, c3);
            }
        }
    }
}

// ---------------------------------------------------------------------------
// Kernel 2: causal flash attention, tf32 mma.sync (unchanged from R5).
// Br=128 (8 warps x 16 rows), Bc=64, double-buffered K/Vt, P via register
// shuffle. 96KB smem, 2 CTAs/SM.
// ---------------------------------------------------------------------------
#define FA_SMEM_BYTES 98304
// float offsets: Q @0 (8192), buf s: K @8192+s*8192, V @12288+s*8192

__global__ __launch_bounds__(256, 2)
void flash_tc(float* __restrict__ out) {
    extern __shared__ float sm[];
    const uint32_t sb = smem_u32(sm);
    const int tid  = threadIdx.x;
    const int lane = tid & 31;
    const int w    = tid >> 5;
    const int bh   = blockIdx.y;
    const int b    = bh >> 4;
    const int h    = bh & (H_ - 1);
    const int qt   = gridDim.x - 1 - blockIdx.x;   // biggest first
    const int q0   = qt * 128;
    const size_t base  = (size_t)bh * T_ * HS_;
    const size_t baseV = (size_t)bh * HS_ * T_;

    const uint32_t qB = sb;

    const int lr = tid >> 4;                 // 0..15
    const int lc = (tid & 15) * 4;           // 0..60
    const int nkt = 2 * qt + 2;

#define FA_LOAD_KV(kn, s_) do {                                                \
    uint32_t kB_ = sb + (8192 + (s_) * 8192) * 4;                              \
    uint32_t vB_ = kB_ + 16384;                                                \
    _Pragma("unroll")                                                          \
    for (int p_ = 0; p_ < 4; p_++) {                                           \
        int r_ = lr + p_ * 16;                                                 \
        cp16(kB_ + sw256(r_, lc), g_k + base + (size_t)((kn) + r_) * HS_ + lc);\
        cp16(vB_ + sw256(r_, lc), g_vt + baseV + (size_t)r_ * T_ + (kn) + lc); \
    }                                                                          \
    asm volatile("cp.async.commit_group;" ::: "memory");                       \
} while (0)

    // Prologue
    {
        uint32_t kB0 = sb + 8192 * 4;
        uint32_t vB0 = kB0 + 16384;
#pragma unroll
        for (int p = 0; p < 8; p++) {
            int r = lr + p * 16;
            cp16(qB + sw256(r, lc), g_q + base + (size_t)(q0 + r) * HS_ + lc);
        }
#pragma unroll
        for (int p = 0; p < 4; p++) {
            int r = lr + p * 16;
            cp16(kB0 + sw256(r, lc), g_k + base + (size_t)r * HS_ + lc);
            cp16(vB0 + sw256(r, lc), g_vt + baseV + (size_t)r * T_ + lc);
        }
        asm volatile("cp.async.commit_group;" ::: "memory");
        FA_LOAD_KV(64, 1);
    }

    float o[8][4];
    float m_[2], l_[2];
    m_[0] = m_[1] = -1e30f;
    l_[0] = l_[1] = 0.0f;
#pragma unroll
    for (int j = 0; j < 8; j++)
#pragma unroll
        for (int e = 0; e < 4; e++) o[j][e] = 0.0f;

    const int aRow  = lane & 15;
    const int aCol  = (lane >> 4) * 4;
    const int bRowO = ((lane & 16) ? 8 : 0) + (lane & 7);
    const int bColO = (lane & 8) ? 4 : 0;
    const int g  = lane >> 2;
    const int t2 = (lane & 3) * 2;
    const int srcA  = (lane & ~3) | ((lane & 3) >> 1);
    const int srcA2 = srcA | 2;
    const bool oddL = lane & 1;

    for (int kt = 0; kt < nkt; kt++) {
        const int k0 = kt * 64;
        const int bufs = kt & 1;
        const uint32_t kB = sb + (8192 + bufs * 8192) * 4;
        const uint32_t vB = kB + 16384;

        if (kt + 1 < nkt) asm volatile("cp.async.wait_group 1;" ::: "memory");
        else              asm volatile("cp.async.wait_group 0;" ::: "memory");
        __syncthreads();

        // S = Q K^T
        float s[8][4];
#pragma unroll
        for (int j = 0; j < 8; j++)
#pragma unroll
            for (int e = 0; e < 4; e++) s[j][e] = 0.0f;

#pragma unroll
        for (int ks = 0; ks < 8; ks++) {
            const int kc = ks * 8;
            uint32_t a[4];
            ldsm4(a[0], a[1], a[2], a[3],
                  qB + sw256(w * 16 + aRow, kc + aCol));
            uint32_t bf[4][4];
#pragma unroll
            for (int p = 0; p < 4; p++)
                ldsm4(bf[p][0], bf[p][1], bf[p][2], bf[p][3],
                      kB + sw256(p * 16 + bRowO, kc + bColO));
#pragma unroll
            for (int j = 0; j < 8; j++)
                mma_tf32(s[j], a,
                         bf[j >> 1][(j & 1) * 2], bf[j >> 1][(j & 1) * 2 + 1]);
        }

        // causal mask (diagonal 128-block = last two kt's)
        if (kt >= 2 * qt) {
#pragma unroll
            for (int j = 0; j < 8; j++)
#pragma unroll
                for (int e = 0; e < 4; e++) {
                    int rg = q0 + w * 16 + g + ((e & 2) ? 8 : 0);
                    int kg = k0 + j * 8 + t2 + (e & 1);
                    if (kg > rg) s[j][e] = -1e30f;
                }
        }

        // online softmax (4-lane row groups)
#pragma unroll
        for (int hf = 0; hf < 2; hf++) {
            const int e0 = hf * 2;
            float mx = -1e30f;
#pragma unroll
            for (int j = 0; j < 8; j++)
                mx = fmaxf(mx, fmaxf(s[j][e0], s[j][e0 + 1]));
            mx = fmaxf(mx, __shfl_xor_sync(0xffffffffu, mx, 1));
            mx = fmaxf(mx, __shfl_xor_sync(0xffffffffu, mx, 2));
            float nm = fmaxf(m_[hf], mx);
            float sum = 0.0f;
#pragma unroll
            for (int j = 0; j < 8; j++) {
                s[j][e0]     = __expf(s[j][e0] - nm);
                s[j][e0 + 1] = __expf(s[j][e0 + 1] - nm);
                sum += s[j][e0] + s[j][e0 + 1];
            }
            sum += __shfl_xor_sync(0xffffffffu, sum, 1);
            sum += __shfl_xor_sync(0xffffffffu, sum, 2);
            float al = __expf(m_[hf] - nm);
            l_[hf] = l_[hf] * al + sum;
            m_[hf] = nm;
#pragma unroll
            for (int j = 0; j < 8; j++) {
                o[j][e0]     *= al;
                o[j][e0 + 1] *= al;
            }
        }

        // round P to tf32 in registers
#pragma unroll
        for (int j = 0; j < 8; j++)
#pragma unroll
            for (int e = 0; e < 4; e++) s[j][e] = to_tf32(s[j][e]);

        // O += P V: A-frag(k-chunk ks) = shuffle of s[ks] C-frag
#pragma unroll
        for (int ks = 0; ks < 8; ks++) {
            const int kc = ks * 8;
            float t00 = __shfl_sync(0xffffffffu, s[ks][0], srcA);
            float t01 = __shfl_sync(0xffffffffu, s[ks][1], srcA);
            float t02 = __shfl_sync(0xffffffffu, s[ks][2], srcA);
            float t03 = __shfl_sync(0xffffffffu, s[ks][3], srcA);
            float u00 = __shfl_sync(0xffffffffu, s[ks][0], srcA2);
            float u01 = __shfl_sync(0xffffffffu, s[ks][1], srcA2);
            float u02 = __shfl_sync(0xffffffffu, s[ks][2], srcA2);
            float u03 = __shfl_sync(0xffffffffu, s[ks][3], srcA2);
            uint32_t a[4];
            a[0] = __float_as_uint(oddL ? t01 : t00);
            a[1] = __float_as_uint(oddL ? t03 : t02);
            a[2] = __float_as_uint(oddL ? u01 : u00);
            a[3] = __float_as_uint(oddL ? u03 : u02);
            uint32_t bf[4][4];
#pragma unroll
            for (int p = 0; p < 4; p++)
                ldsm4(bf[p][0], bf[p][1], bf[p][2], bf[p][3],
                      vB + sw256(p * 16 + bRowO, kc + bColO));
#pragma unroll
            for (int j = 0; j < 8; j++)
                mma_tf32(o[j], a,
                         bf[j >> 1][(j & 1) * 2], bf[j >> 1][(j & 1) * 2 + 1]);
        }

        __syncthreads();     // all warps done reading buf before refill
        if (kt + 2 < nkt) FA_LOAD_KV(k0 + 128, bufs);
    }

    // finalize + write out[b, t, h*64 + d]
    float inv0 = 1.0f / l_[0];
    float inv1 = 1.0f / l_[1];
    int row = q0 + w * 16 + g;
#pragma unroll
    for (int j = 0; j < 8; j++) {
        int d = j * 8 + t2;
        float* p0 = out + (size_t)(b * T_ + row) * C_ + h * HS_ + d;
        *(float2*)p0            = make_float2(o[j][0] * inv0, o[j][1] * inv0);
        *(float2*)(p0 + 8 * C_) = make_float2(o[j][2] * inv1, o[j][3] * inv1);
    }
}

// ---------------------------------------------------------------------------
extern "C" void kernel_launch(void* const* d_in, const int* in_sizes, int n_in,
                              void* d_out, int out_size) {
    const float* x    = (const float*)d_in[0];
    const float* W    = (const float*)d_in[1];
    const float* bias = (const float*)d_in[2];
    float* out = (float*)d_out;

    cudaFuncSetAttribute(qkv_gemm_tc,
                         cudaFuncAttributeMaxDynamicSharedMemorySize,
                         GM_SMEM_BYTES);
    cudaFuncSetAttribute(flash_tc,
                         cudaFuncAttributeMaxDynamicSharedMemorySize,
                         FA_SMEM_BYTES);

    round_inputs<<<(NX4 + NW4) / 256, 256>>>(x, W);

    dim3 g1(N3_ / 256, M_ / 128);           // 12 x 64 = 768 CTAs
    qkv_gemm_tc<<<g1, 256, GM_SMEM_BYTES>>>(bias);

    dim3 g2(T_ / 128, B_ * H_);             // 16 x 64 = 1024 CTAs
    flash_tc<<<g2, 256, FA_SMEM_BYTES>>>(out);
}

// round 7
// speedup vs baseline: 1.0835x; 1.0835x over previous
#include <cuda_runtime.h>
#include <cstdint>

// Problem constants (fixed: B=4, T=2048, C=1024, H=16)
#define B_  4
#define T_  2048
#define C_  1024
#define H_  16
#define HS_ 64
#define M_  (B_ * T_)     // 8192
#define N3_ (3 * C_)      // 3072
#define K_  C_            // 1024

// Scratch (__device__ globals).
__device__ float g_q [(size_t)B_ * H_ * T_ * HS_];   // tf32, pre-scaled 0.125*log2e
__device__ float g_k [(size_t)B_ * H_ * T_ * HS_];   // tf32
__device__ float g_vt[(size_t)B_ * H_ * HS_ * T_];   // tf32, transposed [d][t]
__device__ float g_xr[(size_t)M_ * K_];              // tf32-rounded x
__device__ float g_wr[(size_t)N3_ * K_];             // tf32-rounded W

// ---------------------------------------------------------------------------
__device__ __forceinline__ uint32_t smem_u32(const void* p) {
    uint32_t a;
    asm("{ .reg .u64 t; cvta.to.shared.u64 t, %1; cvt.u32.u64 %0, t; }"
        : "=r"(a) : "l"(p));
    return a;
}
__device__ __forceinline__ float to_tf32(float x) {
    uint32_t u;
    asm("cvt.rna.tf32.f32 %0, %1;" : "=r"(u) : "f"(x));
    return __uint_as_float(u);
}
__device__ __forceinline__ float ex2(float x) {      // 2^x, single MUFU op
    float r;
    asm("ex2.approx.f32 %0, %1;" : "=f"(r) : "f"(x));
    return r;
}
__device__ __forceinline__ void ldsm4(uint32_t& r0, uint32_t& r1,
                                      uint32_t& r2, uint32_t& r3, uint32_t addr) {
    asm volatile("ldmatrix.sync.aligned.m8n8.x4.shared.b16 {%0,%1,%2,%3}, [%4];"
                 : "=r"(r0), "=r"(r1), "=r"(r2), "=r"(r3) : "r"(addr));
}
__device__ __forceinline__ void mma_tf32(float* c, const uint32_t* a,
                                         uint32_t b0, uint32_t b1) {
    asm volatile(
        "mma.sync.aligned.m16n8k8.row.col.f32.tf32.tf32.f32 "
        "{%0,%1,%2,%3}, {%4,%5,%6,%7}, {%8,%9}, {%0,%1,%2,%3};"
        : "+f"(c[0]), "+f"(c[1]), "+f"(c[2]), "+f"(c[3])
        : "r"(a[0]), "r"(a[1]), "r"(a[2]), "r"(a[3]), "r"(b0), "r"(b1));
}
__device__ __forceinline__ void cp16(uint32_t dst_smem, const void* src) {
    asm volatile("cp.async.cg.shared.global [%0], [%1], 16;"
                 :: "r"(dst_smem), "l"(src));
}
// Swizzled byte offsets (XOR bank-quad with row%8). Rows 128B / 256B.
__device__ __forceinline__ uint32_t sw128(int row, int colf) {
    return (uint32_t)(row * 128 + colf * 4) ^ (uint32_t)((row & 7) << 4);
}
__device__ __forceinline__ uint32_t sw256(int row, int colf) {
    return (uint32_t)(row * 256 + colf * 4) ^ (uint32_t)((row & 7) << 4);
}

// ---------------------------------------------------------------------------
// Kernel 0: round x and W to tf32 scratch.
// ---------------------------------------------------------------------------
#define NX4 (M_ * K_ / 4)
#define NW4 (N3_ * K_ / 4)

__global__ __launch_bounds__(256)
void round_inputs(const float* __restrict__ x, const float* __restrict__ W) {
    int i = blockIdx.x * 256 + threadIdx.x;
    if (i < NX4) {
        float4 v = ((const float4*)x)[i];
        v.x = to_tf32(v.x); v.y = to_tf32(v.y);
        v.z = to_tf32(v.z); v.w = to_tf32(v.w);
        ((float4*)g_xr)[i] = v;
    } else {
        int j = i - NX4;
        float4 v = ((const float4*)W)[j];
        v.x = to_tf32(v.x); v.y = to_tf32(v.y);
        v.z = to_tf32(v.z); v.w = to_tf32(v.w);
        ((float4*)g_wr)[j] = v;
    }
}

// ---------------------------------------------------------------------------
// Kernel 1: QKV GEMM, tf32 mma.sync.  CTA 128x128, BK=32, 8 warps (2x4),
// 3-stage cp.async, swizzled pitch-32 smem (96KB) -> 2 CTAs/SM.  (R5 config)
// ---------------------------------------------------------------------------
#define GM_STAGE_B 32768                     // (128+128)*32*4
#define GM_SMEM_BYTES (3 * GM_STAGE_B)       // 98304
#define GM_KT (K_ / 32)                      // 32
#define QSCALE 0.18033688f                   // 0.125 * log2(e)

__global__ __launch_bounds__(256, 2)
void qkv_gemm_tc(const float* __restrict__ bias) {
    extern __shared__ float sm[];
    const uint32_t sb = smem_u32(sm);
    const int tid  = threadIdx.x;
    const int lane = tid & 31;
    const int w    = tid >> 5;
    const int wm   = w >> 2;                 // 0..1 (64-row block)
    const int wn   = w & 3;                  // 0..3 (32-col block)
    const int row0 = blockIdx.y * 128;
    const int col0 = blockIdx.x * 128;

    float acc[4][4][4];
#pragma unroll
    for (int i = 0; i < 4; i++)
#pragma unroll
        for (int j = 0; j < 4; j++)
#pragma unroll
            for (int e = 0; e < 4; e++) acc[i][j][e] = 0.0f;

    const int lr = tid >> 3;                 // 0..31
    const int lc = (tid & 7) * 4;            // 0..28
#define GM_LOAD(kt) do {                                                       \
    uint32_t aOff_ = sb + ((kt) % 3) * GM_STAGE_B;                             \
    uint32_t bOff_ = aOff_ + 16384;                                            \
    const float* Ab_ = g_xr + (size_t)row0 * K_ + (kt) * 32;                   \
    const float* Bb_ = g_wr + (size_t)col0 * K_ + (kt) * 32;                   \
    _Pragma("unroll")                                                          \
    for (int q_ = 0; q_ < 4; q_++) {                                           \
        int r_ = lr + q_ * 32;                                                 \
        cp16(aOff_ + sw128(r_, lc), Ab_ + (size_t)r_ * K_ + lc);               \
        cp16(bOff_ + sw128(r_, lc), Bb_ + (size_t)r_ * K_ + lc);               \
    }                                                                          \
    asm volatile("cp.async.commit_group;" ::: "memory");                       \
} while (0)

    GM_LOAD(0);
    GM_LOAD(1);

    const int aRow  = lane & 15;
    const int aCol  = (lane >> 4) * 4;
    const int bRowO = ((lane & 16) ? 8 : 0) + (lane & 7);
    const int bColO = (lane & 8) ? 4 : 0;

    for (int kt = 0; kt < GM_KT; kt++) {
        if (kt + 1 < GM_KT) asm volatile("cp.async.wait_group 1;" ::: "memory");
        else                asm volatile("cp.async.wait_group 0;" ::: "memory");
        __syncthreads();

        const uint32_t aBase = sb + (kt % 3) * GM_STAGE_B;
        const uint32_t bBase = aBase + 16384;

#pragma unroll
        for (int ks = 0; ks < 4; ks++) {
            const int kc = ks * 8;
            uint32_t a[4][4];
#pragma unroll
            for (int i = 0; i < 4; i++) {
                int row = wm * 64 + i * 16 + aRow;
                ldsm4(a[i][0], a[i][1], a[i][2], a[i][3],
                      aBase + sw128(row, kc + aCol));
            }
            uint32_t bf[2][4];
#pragma unroll
            for (int p = 0; p < 2; p++) {
                int n = wn * 32 + p * 16 + bRowO;
                ldsm4(bf[p][0], bf[p][1], bf[p][2], bf[p][3],
                      bBase + sw128(n, kc + bColO));
            }
#pragma unroll
            for (int i = 0; i < 4; i++)
#pragma unroll
                for (int j = 0; j < 4; j++)
                    mma_tf32(acc[i][j], a[i],
                             bf[j >> 1][(j & 1) * 2], bf[j >> 1][(j & 1) * 2 + 1]);
        }
        if (kt + 2 < GM_KT) GM_LOAD(kt + 2);
    }

    // ---- epilogue ----
    const int g  = lane >> 2;
    const int t2 = (lane & 3) * 2;
    const int sQ = col0 >> 10;                        // 0:q 1:k 2:v
    const int h  = ((col0 + wn * 32) >> 6) & (H_ - 1);

    float rb[4][2];
#pragma unroll
    for (int j = 0; j < 4; j++) {
        rb[j][0] = __ldg(bias + col0 + wn * 32 + j * 8 + t2);
        rb[j][1] = __ldg(bias + col0 + wn * 32 + j * 8 + t2 + 1);
    }

#pragma unroll
    for (int i = 0; i < 4; i++) {
        int m    = row0 + wm * 64 + i * 16 + g;
        int bidx = m >> 11;
        int ti   = m & (T_ - 1);
#pragma unroll
        for (int j = 0; j < 4; j++) {
            int d = ((wn & 1) * 32) + j * 8 + t2;
            float c0 = acc[i][j][0] + rb[j][0];
            float c1 = acc[i][j][1] + rb[j][1];
            float c2 = acc[i][j][2] + rb[j][0];
            float c3 = acc[i][j][3] + rb[j][1];
            if (sQ == 0) {
                c0 *= QSCALE; c1 *= QSCALE; c2 *= QSCALE; c3 *= QSCALE;
            }
            c0 = to_tf32(c0); c1 = to_tf32(c1);
            c2 = to_tf32(c2); c3 = to_tf32(c3);
            if (sQ == 2) {
                float* p = g_vt + (((size_t)bidx * H_ + h) * HS_ + d) * T_ + ti;
                p[0]      = c0;  p[T_]     = c1;
                p[8]      = c2;  p[T_ + 8] = c3;
            } else {
                float* dst = (sQ == 0) ? g_q : g_k;
                float* p = dst + (((size_t)bidx * H_ + h) * T_ + ti) * HS_ + d;
                *(float2*)p             = make_float2(c0, c1);
                *(float2*)(p + 8 * HS_) = make_float2(c2, c3);
            }
        }
    }
}

// ---------------------------------------------------------------------------
// Kernel 2: causal flash attention, tf32 mma.sync (R5 config + base-2 softmax).
// Br=128 (8 warps x 16 rows), Bc=64, double-buffered K/Vt, P via register
// shuffle. 96KB smem, 2 CTAs/SM.
// ---------------------------------------------------------------------------
#define FA_SMEM_BYTES 98304
// float offsets: Q @0 (8192), buf s: K @8192+s*8192, V @12288+s*8192

__global__ __launch_bounds__(256, 2)
void flash_tc(float* __restrict__ out) {
    extern __shared__ float sm[];
    const uint32_t sb = smem_u32(sm);
    const int tid  = threadIdx.x;
    const int lane = tid & 31;
    const int w    = tid >> 5;
    const int bh   = blockIdx.y;
    const int b    = bh >> 4;
    const int h    = bh & (H_ - 1);
    const int qt   = gridDim.x - 1 - blockIdx.x;   // biggest first
    const int q0   = qt * 128;
    const size_t base  = (size_t)bh * T_ * HS_;
    const size_t baseV = (size_t)bh * HS_ * T_;

    const uint32_t qB = sb;

    const int lr = tid >> 4;                 // 0..15
    const int lc = (tid & 15) * 4;           // 0..60
    const int nkt = 2 * qt + 2;

#define FA_LOAD_KV(kn, s_) do {                                                \
    uint32_t kB_ = sb + (8192 + (s_) * 8192) * 4;                              \
    uint32_t vB_ = kB_ + 16384;                                                \
    _Pragma("unroll")                                                          \
    for (int p_ = 0; p_ < 4; p_++) {                                           \
        int r_ = lr + p_ * 16;                                                 \
        cp16(kB_ + sw256(r_, lc), g_k + base + (size_t)((kn) + r_) * HS_ + lc);\
        cp16(vB_ + sw256(r_, lc), g_vt + baseV + (size_t)r_ * T_ + (kn) + lc); \
    }                                                                          \
    asm volatile("cp.async.commit_group;" ::: "memory");                       \
} while (0)

    // Prologue
    {
        uint32_t kB0 = sb + 8192 * 4;
        uint32_t vB0 = kB0 + 16384;
#pragma unroll
        for (int p = 0; p < 8; p++) {
            int r = lr + p * 16;
            cp16(qB + sw256(r, lc), g_q + base + (size_t)(q0 + r) * HS_ + lc);
        }
#pragma unroll
        for (int p = 0; p < 4; p++) {
            int r = lr + p * 16;
            cp16(kB0 + sw256(r, lc), g_k + base + (size_t)r * HS_ + lc);
            cp16(vB0 + sw256(r, lc), g_vt + baseV + (size_t)r * T_ + lc);
        }
        asm volatile("cp.async.commit_group;" ::: "memory");
        FA_LOAD_KV(64, 1);
    }

    float o[8][4];
    float m_[2], l_[2];
    m_[0] = m_[1] = -1e30f;
    l_[0] = l_[1] = 0.0f;
#pragma unroll
    for (int j = 0; j < 8; j++)
#pragma unroll
        for (int e = 0; e < 4; e++) o[j][e] = 0.0f;

    const int aRow  = lane & 15;
    const int aCol  = (lane >> 4) * 4;
    const int bRowO = ((lane & 16) ? 8 : 0) + (lane & 7);
    const int bColO = (lane & 8) ? 4 : 0;
    const int g  = lane >> 2;
    const int t2 = (lane & 3) * 2;
    const int srcA  = (lane & ~3) | ((lane & 3) >> 1);
    const int srcA2 = srcA | 2;
    const bool oddL = lane & 1;

    for (int kt = 0; kt < nkt; kt++) {
        const int k0 = kt * 64;
        const int bufs = kt & 1;
        const uint32_t kB = sb + (8192 + bufs * 8192) * 4;
        const uint32_t vB = kB + 16384;

        if (kt + 1 < nkt) asm volatile("cp.async.wait_group 1;" ::: "memory");
        else              asm volatile("cp.async.wait_group 0;" ::: "memory");
        __syncthreads();

        // S = Q K^T   (base-2 logits: log2e folded into q)
        float s[8][4];
#pragma unroll
        for (int j = 0; j < 8; j++)
#pragma unroll
            for (int e = 0; e < 4; e++) s[j][e] = 0.0f;

#pragma unroll
        for (int ks = 0; ks < 8; ks++) {
            const int kc = ks * 8;
            uint32_t a[4];
            ldsm4(a[0], a[1], a[2], a[3],
                  qB + sw256(w * 16 + aRow, kc + aCol));
            uint32_t bf[4][4];
#pragma unroll
            for (int p = 0; p < 4; p++)
                ldsm4(bf[p][0], bf[p][1], bf[p][2], bf[p][3],
                      kB + sw256(p * 16 + bRowO, kc + bColO));
#pragma unroll
            for (int j = 0; j < 8; j++)
                mma_tf32(s[j], a,
                         bf[j >> 1][(j & 1) * 2], bf[j >> 1][(j & 1) * 2 + 1]);
        }

        // causal mask (diagonal 128-block = last two kt's)
        if (kt >= 2 * qt) {
#pragma unroll
            for (int j = 0; j < 8; j++)
#pragma unroll
                for (int e = 0; e < 4; e++) {
                    int rg = q0 + w * 16 + g + ((e & 2) ? 8 : 0);
                    int kg = k0 + j * 8 + t2 + (e & 1);
                    if (kg > rg) s[j][e] = -1e30f;
                }
        }

        // online softmax in base 2 (4-lane row groups)
#pragma unroll
        for (int hf = 0; hf < 2; hf++) {
            const int e0 = hf * 2;
            float mx = -1e30f;
#pragma unroll
            for (int j = 0; j < 8; j++)
                mx = fmaxf(mx, fmaxf(s[j][e0], s[j][e0 + 1]));
            mx = fmaxf(mx, __shfl_xor_sync(0xffffffffu, mx, 1));
            mx = fmaxf(mx, __shfl_xor_sync(0xffffffffu, mx, 2));
            float nm = fmaxf(m_[hf], mx);
            float sum = 0.0f;
#pragma unroll
            for (int j = 0; j < 8; j++) {
                s[j][e0]     = ex2(s[j][e0] - nm);
                s[j][e0 + 1] = ex2(s[j][e0 + 1] - nm);
                sum += s[j][e0] + s[j][e0 + 1];
            }
            sum += __shfl_xor_sync(0xffffffffu, sum, 1);
            sum += __shfl_xor_sync(0xffffffffu, sum, 2);
            float al = ex2(m_[hf] - nm);
            l_[hf] = l_[hf] * al + sum;
            m_[hf] = nm;
#pragma unroll
            for (int j = 0; j < 8; j++) {
                o[j][e0]     *= al;
                o[j][e0 + 1] *= al;
            }
        }

        // round P to tf32 in registers
#pragma unroll
        for (int j = 0; j < 8; j++)
#pragma unroll
            for (int e = 0; e < 4; e++) s[j][e] = to_tf32(s[j][e]);

        // O += P V: A-frag(k-chunk ks) = shuffle of s[ks] C-frag
#pragma unroll
        for (int ks = 0; ks < 8; ks++) {
            const int kc = ks * 8;
            float t00 = __shfl_sync(0xffffffffu, s[ks][0], srcA);
            float t01 = __shfl_sync(0xffffffffu, s[ks][1], srcA);
            float t02 = __shfl_sync(0xffffffffu, s[ks][2], srcA);
            float t03 = __shfl_sync(0xffffffffu, s[ks][3], srcA);
            float u00 = __shfl_sync(0xffffffffu, s[ks][0], srcA2);
            float u01 = __shfl_sync(0xffffffffu, s[ks][1], srcA2);
            float u02 = __shfl_sync(0xffffffffu, s[ks][2], srcA2);
            float u03 = __shfl_sync(0xffffffffu, s[ks][3], srcA2);
            uint32_t a[4];
            a[0] = __float_as_uint(oddL ? t01 : t00);
            a[1] = __float_as_uint(oddL ? t03 : t02);
            a[2] = __float_as_uint(oddL ? u01 : u00);
            a[3] = __float_as_uint(oddL ? u03 : u02);
            uint32_t bf[4][4];
#pragma unroll
            for (int p = 0; p < 4; p++)
                ldsm4(bf[p][0], bf[p][1], bf[p][2], bf[p][3],
                      vB + sw256(p * 16 + bRowO, kc + bColO));
#pragma unroll
            for (int j = 0; j < 8; j++)
                mma_tf32(o[j], a,
                         bf[j >> 1][(j & 1) * 2], bf[j >> 1][(j & 1) * 2 + 1]);
        }

        __syncthreads();     // all warps done reading buf before refill
        if (kt + 2 < nkt) FA_LOAD_KV(k0 + 128, bufs);
    }

    // finalize + write out[b, t, h*64 + d]
    float inv0 = 1.0f / l_[0];
    float inv1 = 1.0f / l_[1];
    int row = q0 + w * 16 + g;
#pragma unroll
    for (int j = 0; j < 8; j++) {
        int d = j * 8 + t2;
        float* p0 = out + (size_t)(b * T_ + row) * C_ + h * HS_ + d;
        *(float2*)p0            = make_float2(o[j][0] * inv0, o[j][1] * inv0);
        *(float2*)(p0 + 8 * C_) = make_float2(o[j][2] * inv1, o[j][3] * inv1);
    }
}

// ---------------------------------------------------------------------------
extern "C" void kernel_launch(void* const* d_in, const int* in_sizes, int n_in,
                              void* d_out, int out_size) {
    const float* x    = (const float*)d_in[0];
    const float* W    = (const float*)d_in[1];
    const float* bias = (const float*)d_in[2];
    float* out = (float*)d_out;

    cudaFuncSetAttribute(qkv_gemm_tc,
                         cudaFuncAttributeMaxDynamicSharedMemorySize,
                         GM_SMEM_BYTES);
    cudaFuncSetAttribute(flash_tc,
                         cudaFuncAttributeMaxDynamicSharedMemorySize,
                         FA_SMEM_BYTES);

    round_inputs<<<(NX4 + NW4) / 256, 256>>>(x, W);

    dim3 g1(N3_ / 128, M_ / 128);           // 24 x 64 = 1536 CTAs
    qkv_gemm_tc<<<g1, 256, GM_SMEM_BYTES>>>(bias);

    dim3 g2(T_ / 128, B_ * H_);             // 16 x 64 = 1024 CTAs
    flash_tc<<<g2, 256, FA_SMEM_BYTES>>>(out);
}